// round 12
// baseline (speedup 1.0000x reference)
#include <cuda_runtime.h>
#include <cstdint>

#define HH 2048
#define WW 2048
#define PW 2050                    // padded width/height (+1 border each side)
#define NPIX (HH * WW)
#define NITER 96                   // early-exit cap

typedef unsigned long long u64;

// ---- persistent device state (static device globals; no allocations) ----
__device__ unsigned char g_P[PW * PW];   // padded current bitmap (0/1)
__device__ unsigned char g_Q[PW * PW];   // padded next bitmap
__device__ int g_stop;                   // 1 => converged
__device__ int g_changed;                // any removal in current full iteration

// ============================================================
// Kernel 0: reset flags (single thread, runs first)
// ============================================================
__global__ void reset_kernel() {
    g_stop = 0; g_changed = 0;
}

// ============================================================
// Kernel 1: grayscale + threshold into padded byte image.
// Strict left-assoc unfused: (0.2989*r + 0.587*g) + 0.114*b
// (XLA emits separate mul/add HLO; LLVM does not contract them)
// ============================================================
__global__ void binarize_kernel(const float* __restrict__ img) {
    int idx = blockIdx.x * blockDim.x + threadIdx.x;    // 0..NPIX-1
    int r = idx >> 11;          // WW == 2048 == 2^11
    int c = idx & 2047;
    float rr = img[idx];
    float gg = img[idx + NPIX];
    float bb = img[idx + 2 * NPIX];
    float gray = __fadd_rn(__fadd_rn(__fmul_rn(0.2989f, rr),
                                     __fmul_rn(0.587f,  gg)),
                           __fmul_rn(0.114f, bb));
    g_P[(r + 1) * PW + (c + 1)] = (gray > 0.5f) ? 1 : 0;
}

// ============================================================
// One Zhang–Suen sub-step: literal transcription of the reference
// ============================================================
__device__ __forceinline__ void sub_body(const unsigned char* __restrict__ s,
                                         unsigned char* __restrict__ d,
                                         bool first) {
    int idx = blockIdx.x * blockDim.x + threadIdx.x;    // 0..NPIX-1
    int r = idx >> 11;
    int c = idx & 2047;
    const unsigned char* p = s + (r + 1) * PW + (c + 1);

    int b  = p[0];
    int P2 = p[-PW];        // N
    int P3 = p[-PW + 1];    // NE
    int P4 = p[1];          // E
    int P5 = p[PW + 1];     // SE
    int P6 = p[PW];         // S
    int P7 = p[PW - 1];     // SW
    int P8 = p[-1];         // W
    int P9 = p[-PW - 1];    // NW

    int B = P2 + P3 + P4 + P5 + P6 + P7 + P8 + P9;
    int A = (1 - P2) * P3 + (1 - P3) * P4 + (1 - P4) * P5 + (1 - P5) * P6
          + (1 - P6) * P7 + (1 - P7) * P8 + (1 - P8) * P9 + (1 - P9) * P2;

    int c1 = (B >= 2) && (B <= 6);
    int c2 = (A == 1);
    int c3 = ((first ? P2 * P4 * P6 : P2 * P4 * P8) == 0);
    int c4 = ((first ? P4 * P6 * P8 : P2 * P6 * P8) == 0);

    int remove = b & c1 & c2 & c3 & c4;
    int nv = remove ? 0 : b;

    d[(r + 1) * PW + (c + 1)] = (unsigned char)nv;
    if (remove) g_changed = 1;          // racy idempotent store
}

// Parity: sub1: P -> Q (first), sub2: Q -> P (second).
// Converged state always lives in g_P.
__global__ void __launch_bounds__(256) substep1_kernel() {
    if (__ldcg(&g_stop)) return;
    sub_body(g_P, g_Q, true);
}
__global__ void __launch_bounds__(256) substep2_kernel() {
    if (__ldcg(&g_stop)) return;
    sub_body(g_Q, g_P, false);
}

// One-thread convergence check after each full iteration
__global__ void check_kernel() {
    if (!g_stop) {
        if (!g_changed) g_stop = 1;
        else            g_changed = 0;
    }
}

// ============================================================
// Output: padded bytes -> FLOAT32 image (0.0f / 1.0f).
// Writing float values is the experiment of this round: if the
// harness's __output__ dtype is float32, int writes read as
// denormals ~= 0 and rel_err is exactly 1.0 forever — matching
// all nine previous rounds.
// ============================================================
__global__ void output_kernel(float* __restrict__ out) {
    int idx = blockIdx.x * blockDim.x + threadIdx.x;
    int r = idx >> 11;
    int c = idx & 2047;
    out[idx] = (float)g_P[(r + 1) * PW + (c + 1)];
}

// ============================================================
extern "C" void kernel_launch(void* const* d_in, const int* in_sizes, int n_in,
                              void* d_out, int out_size) {
    const float* img = (const float*)d_in[0];
    float* out = (float*)d_out;

    reset_kernel<<<1, 1>>>();
    binarize_kernel<<<NPIX / 256, 256>>>(img);
    for (int i = 0; i < NITER; i++) {
        substep1_kernel<<<NPIX / 256, 256>>>();
        substep2_kernel<<<NPIX / 256, 256>>>();
        check_kernel<<<1, 1>>>();
    }
    output_kernel<<<NPIX / 256, 256>>>(out);
}

// round 13
// speedup vs baseline: 16.6597x; 16.6597x over previous
#include <cuda_runtime.h>
#include <cstdint>

#define HH 2048
#define WW 2048
#define W64 32                 // 64-bit words per row
#define NWORDS (HH * W64)      // 65536 words = 512 KB per bitmap
#define NPIX (HH * WW)
#define NITER 64               // forced full iterations (I_conv est. 25-35; no-ops after)

typedef unsigned long long u64;

// ---- persistent device state (device globals; no allocations) ----
__device__ u64 g_A[NWORDS];
__device__ u64 g_B[NWORDS];

// ============================================================
// Kernel 1: grayscale + threshold + bitpack (1 bit/pixel)
// Grayscale bit-identical to the R12 passing version.
// ============================================================
__global__ void bitpack_kernel(const float* __restrict__ img) {
    int idx = blockIdx.x * blockDim.x + threadIdx.x;      // pixel linear index
    float rr = img[idx];
    float gg = img[idx + NPIX];
    float bb = img[idx + 2 * NPIX];
    float gray = __fadd_rn(__fadd_rn(__fmul_rn(0.2989f, rr),
                                     __fmul_rn(0.587f,  gg)),
                           __fmul_rn(0.114f, bb));
    unsigned m = __ballot_sync(0xFFFFFFFFu, gray > 0.5f);
    if ((threadIdx.x & 31) == 0)
        ((unsigned*)g_A)[idx >> 5] = m;   // little-endian u32 pair = u64, LSB = lowest col
}

// ============================================================
// Zhang–Suen sub-step, bit-parallel over 64 pixels/word
// ============================================================
#define MAJ(a, b, c) (((a) & (b)) | ((c) & ((a) ^ (b))))

__device__ __forceinline__ void substep_body(const u64* __restrict__ src,
                                             u64* __restrict__ dst,
                                             bool first) {
    int w = blockIdx.x * blockDim.x + threadIdx.x;   // one word per thread
    int r = w >> 5;
    int c = w & 31;

    u64 cc = __ldcg(src + w);
    if (cc == 0ULL) { __stcg(dst + w, 0ULL); return; }

    u64 cl = (c > 0)       ? __ldcg(src + w - 1)  : 0ULL;
    u64 cr = (c < W64 - 1) ? __ldcg(src + w + 1)  : 0ULL;
    u64 uc = 0, ul = 0, ur = 0, dc = 0, dl = 0, dr = 0;
    if (r > 0) {
        uc = __ldcg(src + w - W64);
        ul = (c > 0)       ? __ldcg(src + w - W64 - 1) : 0ULL;
        ur = (c < W64 - 1) ? __ldcg(src + w - W64 + 1) : 0ULL;
    }
    if (r < HH - 1) {
        dc = __ldcg(src + w + W64);
        dl = (c > 0)       ? __ldcg(src + w + W64 - 1) : 0ULL;
        dr = (c < W64 - 1) ? __ldcg(src + w + W64 + 1) : 0ULL;
    }

    // neighbor masks: bit i = that neighbor of pixel (r, c*64+i)
    u64 n2 = uc;                         // N
    u64 n3 = (uc >> 1) | (ur << 63);     // NE
    u64 n4 = (cc >> 1) | (cr << 63);     // E
    u64 n5 = (dc >> 1) | (dr << 63);     // SE
    u64 n6 = dc;                         // S
    u64 n7 = (dc << 1) | (dl >> 63);     // SW
    u64 n8 = (cc << 1) | (cl >> 63);     // W
    u64 n9 = (uc << 1) | (ul >> 63);     // NW

    // ---- B = popcount of 8 neighbors (CSA tree); need 2 <= B <= 6 ----
    u64 s1 = n2 ^ n3 ^ n4, c1v = MAJ(n2, n3, n4);
    u64 s2 = n5 ^ n6 ^ n7, c2v = MAJ(n5, n6, n7);
    u64 s3 = n8 ^ n9,      c3v = n8 & n9;
    u64 b0 = s1 ^ s2 ^ s3;
    u64 k1 = MAJ(s1, s2, s3);
    u64 wv = c1v ^ c2v ^ c3v, xv = MAJ(c1v, c2v, c3v);
    u64 b1 = wv ^ k1, mm = wv & k1;
    u64 b2 = xv ^ mm, b3 = xv & mm;
    u64 condB = (b1 | b2) & ~b3 & ~(b0 & b1 & b2);

    // ---- A = # of 0->1 transitions around (P2..P9,P2); need A == 1 ----
    u64 t0 = ~n2 & n3, t1 = ~n3 & n4, t2 = ~n4 & n5, t3 = ~n5 & n6;
    u64 t4 = ~n6 & n7, t5 = ~n7 & n8, t6 = ~n8 & n9, t7 = ~n9 & n2;
    u64 as1 = t0 ^ t1 ^ t2, ac1 = MAJ(t0, t1, t2);
    u64 as2 = t3 ^ t4 ^ t5, ac2 = MAJ(t3, t4, t5);
    u64 as3 = t6 ^ t7,      ac3 = t6 & t7;
    u64 a0 = as1 ^ as2 ^ as3;
    u64 e1 = MAJ(as1, as2, as3);
    u64 yy = ac1 ^ ac2 ^ ac3, zz = MAJ(ac1, ac2, ac3);
    u64 a1 = yy ^ e1; u64 qq = yy & e1;
    u64 a2 = zz ^ qq; u64 a3 = zz & qq;
    u64 condA = a0 & ~a1 & ~a2 & ~a3;

    // ---- direction conditions ----
    u64 c34 = first ? (~(n2 & n4 & n6) & ~(n4 & n6 & n8))
                    : (~(n2 & n4 & n8) & ~(n2 & n6 & n8));

    u64 remove = cc & condB & condA & c34;
    __stcg(dst + w, cc & ~remove);
}

// Parity: sub1: A -> B (first), sub2: B -> A (second).
// After any number of full iterations the state lives in g_A.
__global__ void __launch_bounds__(256) substep1_kernel() {
    substep_body(g_A, g_B, true);
}
__global__ void __launch_bounds__(256) substep2_kernel() {
    substep_body(g_B, g_A, false);
}

// ============================================================
// Output: bits -> float32 image (4 pixels / thread, float4 store)
// ============================================================
__global__ void unpack_kernel(float* __restrict__ out) {
    int t = blockIdx.x * blockDim.x + threadIdx.x;
    int idx = t * 4;                      // 4 consecutive pixels, same word
    u64 wv = g_A[idx >> 6];
    unsigned sh = (unsigned)(idx & 63);
    float4 v;
    v.x = (float)((wv >> (sh + 0)) & 1ULL);
    v.y = (float)((wv >> (sh + 1)) & 1ULL);
    v.z = (float)((wv >> (sh + 2)) & 1ULL);
    v.w = (float)((wv >> (sh + 3)) & 1ULL);
    ((float4*)out)[t] = v;
}

// ============================================================
extern "C" void kernel_launch(void* const* d_in, const int* in_sizes, int n_in,
                              void* d_out, int out_size) {
    const float* img = (const float*)d_in[0];
    float* out = (float*)d_out;

    bitpack_kernel<<<NPIX / 256, 256>>>(img);
    for (int i = 0; i < NITER; i++) {
        substep1_kernel<<<NWORDS / 256, 256>>>();
        substep2_kernel<<<NWORDS / 256, 256>>>();
    }
    unpack_kernel<<<NPIX / 4 / 256, 256>>>(out);
}

// round 14
// speedup vs baseline: 27.1179x; 1.6278x over previous
#include <cuda_runtime.h>
#include <cstdint>

#define HH 2048
#define WW 2048
#define W64 32                 // 64-bit words per row
#define NWORDS (HH * W64)      // 65536 words = 512 KB per bitmap
#define NPIX (HH * WW)
#define NITER 64               // cap; measured I_conv ~ 44

typedef unsigned long long u64;

// ---- persistent device state (device globals; no allocations) ----
__device__ u64 g_A[NWORDS];
__device__ u64 g_B[NWORDS];
__device__ int g_chg[NITER];   // g_chg[i] = 1 iff full iteration i removed any pixel

// ============================================================
// Kernel 1: grayscale + threshold + bitpack (1 bit/pixel).
// Also zeroes the per-iteration change flags (replay-safe).
// ============================================================
__global__ void bitpack_kernel(const float* __restrict__ img) {
    int idx = blockIdx.x * blockDim.x + threadIdx.x;      // pixel linear index
    if (idx < NITER) g_chg[idx] = 0;
    float rr = img[idx];
    float gg = img[idx + NPIX];
    float bb = img[idx + 2 * NPIX];
    float gray = __fadd_rn(__fadd_rn(__fmul_rn(0.2989f, rr),
                                     __fmul_rn(0.587f,  gg)),
                           __fmul_rn(0.114f, bb));
    unsigned m = __ballot_sync(0xFFFFFFFFu, gray > 0.5f);
    if ((threadIdx.x & 31) == 0)
        ((unsigned*)g_A)[idx >> 5] = m;   // little-endian u32 pair = u64, LSB = lowest col
}

// ============================================================
// Zhang–Suen sub-step, bit-parallel over 64 pixels/word.
// Default (L1-cached) loads: safe because L1D is flushed at
// every kernel launch, and the launch boundary is the sync.
// ============================================================
#define MAJ(a, b, c) (((a) & (b)) | ((c) & ((a) ^ (b))))

__device__ __forceinline__ void substep_body(const u64* __restrict__ src,
                                             u64* __restrict__ dst,
                                             bool first, int iter) {
    int w = blockIdx.x * blockDim.x + threadIdx.x;   // one word per thread
    int r = w >> 5;
    int c = w & 31;

    u64 cc = src[w];
    if (cc == 0ULL) { dst[w] = 0ULL; return; }

    u64 cl = (c > 0)       ? src[w - 1]  : 0ULL;
    u64 cr = (c < W64 - 1) ? src[w + 1]  : 0ULL;
    u64 uc = 0, ul = 0, ur = 0, dc = 0, dl = 0, dr = 0;
    if (r > 0) {
        uc = src[w - W64];
        ul = (c > 0)       ? src[w - W64 - 1] : 0ULL;
        ur = (c < W64 - 1) ? src[w - W64 + 1] : 0ULL;
    }
    if (r < HH - 1) {
        dc = src[w + W64];
        dl = (c > 0)       ? src[w + W64 - 1] : 0ULL;
        dr = (c < W64 - 1) ? src[w + W64 + 1] : 0ULL;
    }

    // neighbor masks: bit i = that neighbor of pixel (r, c*64+i)
    u64 n2 = uc;                         // N
    u64 n3 = (uc >> 1) | (ur << 63);     // NE
    u64 n4 = (cc >> 1) | (cr << 63);     // E
    u64 n5 = (dc >> 1) | (dr << 63);     // SE
    u64 n6 = dc;                         // S
    u64 n7 = (dc << 1) | (dl >> 63);     // SW
    u64 n8 = (cc << 1) | (cl >> 63);     // W
    u64 n9 = (uc << 1) | (ul >> 63);     // NW

    // ---- B = popcount of 8 neighbors (CSA tree); need 2 <= B <= 6 ----
    u64 s1 = n2 ^ n3 ^ n4, c1v = MAJ(n2, n3, n4);
    u64 s2 = n5 ^ n6 ^ n7, c2v = MAJ(n5, n6, n7);
    u64 s3 = n8 ^ n9,      c3v = n8 & n9;
    u64 b0 = s1 ^ s2 ^ s3;
    u64 k1 = MAJ(s1, s2, s3);
    u64 wv = c1v ^ c2v ^ c3v, xv = MAJ(c1v, c2v, c3v);
    u64 b1 = wv ^ k1, mm = wv & k1;
    u64 b2 = xv ^ mm, b3 = xv & mm;
    u64 condB = (b1 | b2) & ~b3 & ~(b0 & b1 & b2);

    // ---- A = # of 0->1 transitions around (P2..P9,P2); need A == 1 ----
    u64 t0 = ~n2 & n3, t1 = ~n3 & n4, t2 = ~n4 & n5, t3 = ~n5 & n6;
    u64 t4 = ~n6 & n7, t5 = ~n7 & n8, t6 = ~n8 & n9, t7 = ~n9 & n2;
    u64 as1 = t0 ^ t1 ^ t2, ac1 = MAJ(t0, t1, t2);
    u64 as2 = t3 ^ t4 ^ t5, ac2 = MAJ(t3, t4, t5);
    u64 as3 = t6 ^ t7,      ac3 = t6 & t7;
    u64 a0 = as1 ^ as2 ^ as3;
    u64 e1 = MAJ(as1, as2, as3);
    u64 yy = ac1 ^ ac2 ^ ac3, zz = MAJ(ac1, ac2, ac3);
    u64 a1 = yy ^ e1; u64 qq = yy & e1;
    u64 a2 = zz ^ qq; u64 a3 = zz & qq;
    u64 condA = a0 & ~a1 & ~a2 & ~a3;

    // ---- direction conditions ----
    u64 c34 = first ? (~(n2 & n4 & n6) & ~(n4 & n6 & n8))
                    : (~(n2 & n4 & n8) & ~(n2 & n6 & n8));

    u64 remove = cc & condB & condA & c34;
    dst[w] = cc & ~remove;
    if (remove) g_chg[iter] = 1;     // racy idempotent store
}

// Parity: sub1: A -> B (first), sub2: B -> A (second).
// Early exit: if the previous full iteration removed nothing, we are at the
// fixed point; every later launch returns immediately and g_A holds the result.
__global__ void __launch_bounds__(256) substep1_kernel(int iter) {
    if (iter > 0 && g_chg[iter - 1] == 0) return;
    substep_body(g_A, g_B, true, iter);
}
__global__ void __launch_bounds__(256) substep2_kernel(int iter) {
    if (iter > 0 && g_chg[iter - 1] == 0) return;
    substep_body(g_B, g_A, false, iter);
}

// ============================================================
// Output: bits -> float32 image (4 pixels / thread, float4 store)
// ============================================================
__global__ void unpack_kernel(float* __restrict__ out) {
    int t = blockIdx.x * blockDim.x + threadIdx.x;
    int idx = t * 4;                      // 4 consecutive pixels, same word
    u64 wv = g_A[idx >> 6];
    unsigned sh = (unsigned)(idx & 63);
    float4 v;
    v.x = (float)((wv >> (sh + 0)) & 1ULL);
    v.y = (float)((wv >> (sh + 1)) & 1ULL);
    v.z = (float)((wv >> (sh + 2)) & 1ULL);
    v.w = (float)((wv >> (sh + 3)) & 1ULL);
    ((float4*)out)[t] = v;
}

// ============================================================
extern "C" void kernel_launch(void* const* d_in, const int* in_sizes, int n_in,
                              void* d_out, int out_size) {
    const float* img = (const float*)d_in[0];
    float* out = (float*)d_out;

    bitpack_kernel<<<NPIX / 256, 256>>>(img);
    for (int i = 0; i < NITER; i++) {
        substep1_kernel<<<NWORDS / 256, 256>>>(i);
        substep2_kernel<<<NWORDS / 256, 256>>>(i);
    }
    unpack_kernel<<<NPIX / 4 / 256, 256>>>(out);
}

// round 15
// speedup vs baseline: 88.2672x; 3.2549x over previous
#include <cuda_runtime.h>
#include <cstdint>

#define HH 2048
#define WW 2048
#define W64 32                    // 64-bit words per row
#define NWORDS (HH * W64)         // 65536 words = 512 KB per bitmap
#define NPIX (HH * WW)

#define TROWS 32                  // owned rows per block
#define TWORDS 8                  // owned words per block
#define HROWS 8                   // halo rows each side (= NSUB)
#define SROWS (TROWS + 2 * HROWS) // 48
#define SWORDS (TWORDS + 2)       // 10 (1 halo word each side = 64-bit halo)
#define SN (SROWS * SWORDS)       // 480 words of smem per buffer
#define NSUB 8                    // substeps fused per launch = 4 full iterations
#define NGROUPS 16                // 16 * 4 = 64 full-iteration cap (I_conv ~ 44)
#define NBLKX (W64 / TWORDS)      // 4
#define NBLKY (HH / TROWS)        // 64

typedef unsigned long long u64;

// ---- persistent device state (device globals; no allocations) ----
__device__ u64 g_A[NWORDS];
__device__ int g_chg[NGROUPS];    // g_chg[g] = 1 iff group g removed any owned pixel

// ============================================================
// Kernel 1: grayscale + threshold + bitpack (1 bit/pixel).
// Also zeroes the per-group change flags (replay-safe).
// ============================================================
__global__ void bitpack_kernel(const float* __restrict__ img) {
    int idx = blockIdx.x * blockDim.x + threadIdx.x;      // pixel linear index
    if (idx < NGROUPS) g_chg[idx] = 0;
    float rr = img[idx];
    float gg = img[idx + NPIX];
    float bb = img[idx + 2 * NPIX];
    float gray = __fadd_rn(__fadd_rn(__fmul_rn(0.2989f, rr),
                                     __fmul_rn(0.587f,  gg)),
                           __fmul_rn(0.114f, bb));
    unsigned m = __ballot_sync(0xFFFFFFFFu, gray > 0.5f);
    if ((threadIdx.x & 31) == 0)
        ((unsigned*)g_A)[idx >> 5] = m;   // little-endian u32 pair = u64, LSB = lowest col
}

// ============================================================
// Bit-parallel Zhang–Suen word update (64 pixels at once)
// ============================================================
#define MAJ(a, b, c) (((a) & (b)) | ((c) & ((a) ^ (b))))

__device__ __forceinline__ u64 zs_word(u64 cc,
                                       u64 cl, u64 cr,
                                       u64 uc, u64 ul, u64 ur,
                                       u64 dc, u64 dl, u64 dr,
                                       bool first) {
    // neighbor masks: bit i = that neighbor of pixel i
    u64 n2 = uc;                         // N
    u64 n3 = (uc >> 1) | (ur << 63);     // NE
    u64 n4 = (cc >> 1) | (cr << 63);     // E
    u64 n5 = (dc >> 1) | (dr << 63);     // SE
    u64 n6 = dc;                         // S
    u64 n7 = (dc << 1) | (dl >> 63);     // SW
    u64 n8 = (cc << 1) | (cl >> 63);     // W
    u64 n9 = (uc << 1) | (ul >> 63);     // NW

    // ---- B = popcount of 8 neighbors (CSA tree); need 2 <= B <= 6 ----
    u64 s1 = n2 ^ n3 ^ n4, c1v = MAJ(n2, n3, n4);
    u64 s2 = n5 ^ n6 ^ n7, c2v = MAJ(n5, n6, n7);
    u64 s3 = n8 ^ n9,      c3v = n8 & n9;
    u64 b0 = s1 ^ s2 ^ s3;
    u64 k1 = MAJ(s1, s2, s3);
    u64 wv = c1v ^ c2v ^ c3v, xv = MAJ(c1v, c2v, c3v);
    u64 b1 = wv ^ k1, mm = wv & k1;
    u64 b2 = xv ^ mm, b3 = xv & mm;
    u64 condB = (b1 | b2) & ~b3 & ~(b0 & b1 & b2);

    // ---- A = # of 0->1 transitions around (P2..P9,P2); need A == 1 ----
    u64 t0 = ~n2 & n3, t1 = ~n3 & n4, t2 = ~n4 & n5, t3 = ~n5 & n6;
    u64 t4 = ~n6 & n7, t5 = ~n7 & n8, t6 = ~n8 & n9, t7 = ~n9 & n2;
    u64 as1 = t0 ^ t1 ^ t2, ac1 = MAJ(t0, t1, t2);
    u64 as2 = t3 ^ t4 ^ t5, ac2 = MAJ(t3, t4, t5);
    u64 as3 = t6 ^ t7,      ac3 = t6 & t7;
    u64 a0 = as1 ^ as2 ^ as3;
    u64 e1 = MAJ(as1, as2, as3);
    u64 yy = ac1 ^ ac2 ^ ac3, zz = MAJ(ac1, ac2, ac3);
    u64 a1 = yy ^ e1; u64 qq = yy & e1;
    u64 a2 = zz ^ qq; u64 a3 = zz & qq;
    u64 condA = a0 & ~a1 & ~a2 & ~a3;

    // ---- direction conditions ----
    u64 c34 = first ? (~(n2 & n4 & n6) & ~(n4 & n6 & n8))
                    : (~(n2 & n4 & n8) & ~(n2 & n6 & n8));

    return cc & ~(cc & condB & condA & c34);
}

// ============================================================
// Fused kernel: 8 substeps (4 full Zhang–Suen iterations) in smem.
// Halo = 8 rows / 64 cols >= influence radius of 8 substeps, so the
// owned interior is bit-exact vs. the global iteration.
// ============================================================
__global__ void __launch_bounds__(256) fused_kernel(int group) {
    if (group > 0 && g_chg[group - 1] == 0) return;   // fixed point reached

    __shared__ u64 sA[SN], sB[SN];

    int bx = blockIdx.x & (NBLKX - 1);        // word-column of tile
    int by = blockIdx.x >> 2;                 // row-block of tile
    int R0 = by * TROWS - HROWS;              // global row of smem row 0
    int C0 = bx * TWORDS - 1;                 // global word-col of smem col 0

    // ---- load tile + halo (clamp outside image to 0 = true zero pad) ----
    for (int i = threadIdx.x; i < SN; i += 256) {
        int sr = i / SWORDS, sc = i - (i / SWORDS) * SWORDS;
        int gr = R0 + sr, gc = C0 + sc;
        u64 v = 0ULL;
        if (gr >= 0 && gr < HH && gc >= 0 && gc < W64)
            v = g_A[gr * W64 + gc];
        sA[i] = v;
    }
    __syncthreads();

    // ---- 8 substeps, ping-pong in smem ----
    u64* src = sA;
    u64* dst = sB;
    #pragma unroll
    for (int s = 0; s < NSUB; s++) {
        bool first = ((s & 1) == 0);
        for (int i = threadIdx.x; i < SN; i += 256) {
            int sr = i / SWORDS, sc = i - (i / SWORDS) * SWORDS;
            u64 cc = src[i];
            u64 nv;
            if (cc == 0ULL) {
                nv = 0ULL;
            } else {
                u64 cl = (sc > 0)          ? src[i - 1]          : 0ULL;
                u64 cr = (sc < SWORDS - 1) ? src[i + 1]          : 0ULL;
                u64 uc = 0, ul = 0, ur = 0, dc = 0, dl = 0, dr = 0;
                if (sr > 0) {
                    uc = src[i - SWORDS];
                    ul = (sc > 0)          ? src[i - SWORDS - 1] : 0ULL;
                    ur = (sc < SWORDS - 1) ? src[i - SWORDS + 1] : 0ULL;
                }
                if (sr < SROWS - 1) {
                    dc = src[i + SWORDS];
                    dl = (sc > 0)          ? src[i + SWORDS - 1] : 0ULL;
                    dr = (sc < SWORDS - 1) ? src[i + SWORDS + 1] : 0ULL;
                }
                nv = zs_word(cc, cl, cr, uc, ul, ur, dc, dl, dr, first);
            }
            dst[i] = nv;
        }
        __syncthreads();
        u64* t = src; src = dst; dst = t;
    }

    // ---- store owned region; detect any change vs. group start ----
    bool changed = false;
    for (int i = threadIdx.x; i < TROWS * TWORDS; i += 256) {
        int tr = i / TWORDS, tc = i - (i / TWORDS) * TWORDS;
        int sr = tr + HROWS, sc = tc + 1;
        int g  = (by * TROWS + tr) * W64 + (bx * TWORDS + tc);
        u64 v  = src[sr * SWORDS + sc];
        u64 old = g_A[g];
        if (v != old) { changed = true; g_A[g] = v; }
    }
    if (__syncthreads_or(changed ? 1 : 0) && threadIdx.x == 0)
        g_chg[group] = 1;
}

// ============================================================
// Output: bits -> float32 image (4 pixels / thread, float4 store)
// ============================================================
__global__ void unpack_kernel(float* __restrict__ out) {
    int t = blockIdx.x * blockDim.x + threadIdx.x;
    int idx = t * 4;                      // 4 consecutive pixels, same word
    u64 wv = g_A[idx >> 6];
    unsigned sh = (unsigned)(idx & 63);
    float4 v;
    v.x = (float)((wv >> (sh + 0)) & 1ULL);
    v.y = (float)((wv >> (sh + 1)) & 1ULL);
    v.z = (float)((wv >> (sh + 2)) & 1ULL);
    v.w = (float)((wv >> (sh + 3)) & 1ULL);
    ((float4*)out)[t] = v;
}

// ============================================================
extern "C" void kernel_launch(void* const* d_in, const int* in_sizes, int n_in,
                              void* d_out, int out_size) {
    const float* img = (const float*)d_in[0];
    float* out = (float*)d_out;

    bitpack_kernel<<<NPIX / 256, 256>>>(img);
    for (int g = 0; g < NGROUPS; g++)
        fused_kernel<<<NBLKX * NBLKY, 256>>>(g);
    unpack_kernel<<<NPIX / 4 / 256, 256>>>(out);
}